// round 6
// baseline (speedup 1.0000x reference)
#include <cuda_runtime.h>
#include <math.h>
#include <stdint.h>

// Problem constants
#define T      512
#define HDIM   2048
#define NE     32
#define TOPK   8
#define IDIM   1408
#define NGRP   8
#define TKG    4
#define CAP    256
#define RSF    2.5f
#define ISH    2816

// SMEM row stride in words: 16 data + 4 pad (80B, 16B aligned, conflict-free)
#define RS 20

// ---------------- device scratch ----------------
__device__ int   g_topk_ids[T * TOPK];
__device__ float g_topk_w[T * TOPK];
__device__ int   g_assign_slot[T * TOPK];
__device__ int   g_slot_token[NE * CAP];
__device__ int   g_counts[NE];
__device__ float g_h1[NE * CAP * IDIM];
__device__ float g_y [NE * CAP * HDIM];
__device__ float g_hs[T * ISH];

#define PTR_PARAM 0
#define PTR_H1    1
#define PTR_Y     2
#define PTR_HS    3

template <int M>
__device__ __forceinline__ float* resolve(float* p) {
    if constexpr (M == PTR_H1) return g_h1;
    else if constexpr (M == PTR_Y) return g_y;
    else if constexpr (M == PTR_HS) return g_hs;
    else return p;
}

// ---------------- helpers ----------------
__device__ __forceinline__ unsigned f2tf(float f) {
    unsigned r; asm("cvt.rna.tf32.f32 %0, %1;" : "=r"(r) : "f"(f)); return r;
}
__device__ __forceinline__ void mma_tf32(float* c, uint4 a, unsigned b0, unsigned b1) {
    asm("mma.sync.aligned.m16n8k8.row.col.f32.tf32.tf32.f32 "
        "{%0,%1,%2,%3},{%4,%5,%6,%7},{%8,%9},{%0,%1,%2,%3};"
        : "+f"(c[0]), "+f"(c[1]), "+f"(c[2]), "+f"(c[3])
        : "r"(a.x), "r"(a.y), "r"(a.z), "r"(a.w), "r"(b0), "r"(b1));
}
__device__ __forceinline__ uint4 ldsm4(unsigned addr) {
    uint4 r;
    asm volatile("ldmatrix.sync.aligned.m8n8.x4.shared.b16 {%0,%1,%2,%3}, [%4];"
                 : "=r"(r.x), "=r"(r.y), "=r"(r.z), "=r"(r.w) : "r"(addr));
    return r;
}
__device__ __forceinline__ float silu_mul(float g, float u) {
    return (g / (1.f + expf(-g))) * u;
}
__device__ __forceinline__ uint4 cvt4(float4 v) {
    return make_uint4(f2tf(v.x), f2tf(v.y), f2tf(v.z), f2tf(v.w));
}

// ---------------- routing ----------------
__global__ void routing_kernel(const float* __restrict__ x,
                               const float* __restrict__ gw,
                               const float* __restrict__ bias) {
    int t    = blockIdx.x;
    int tid  = threadIdx.x;
    int lane = tid & 31;
    int wid  = tid >> 5;

    __shared__ float part[8][32];
    const float* xr = x + (long long)t * HDIM;
    float acc = 0.f;
    int h0 = wid * (HDIM / 8);
    for (int h = h0; h < h0 + HDIM / 8; ++h)
        acc += xr[h] * gw[h * NE + lane];
    part[wid][lane] = acc;
    __syncthreads();

    if (wid != 0) return;

    float logit = 0.f;
#pragma unroll
    for (int w = 0; w < 8; ++w) logit += part[w][lane];

    float s  = 1.f / (1.f + expf(-logit));
    float sb = s + bias[lane];

    float p   = __shfl_xor_sync(0xffffffffu, sb, 1);
    float hi  = fmaxf(sb, p), lo = fminf(sb, p);
    float hi2 = __shfl_xor_sync(0xffffffffu, hi, 2);
    float lo2 = __shfl_xor_sync(0xffffffffu, lo, 2);
    float gs  = (hi >= hi2) ? hi + fmaxf(hi2, lo) : hi2 + fmaxf(hi, lo2);

    int g = lane >> 2;
    int grank = 0;
#pragma unroll
    for (int g2 = 0; g2 < NGRP; ++g2) {
        float og = __shfl_sync(0xffffffffu, gs, g2 * 4);
        if (og > gs || (og == gs && g2 < g)) ++grank;
    }
    float cand = (grank < TKG) ? sb : -INFINITY;

    float v = cand;
    int   sel_e = 0; float sel_w = 0.f;
#pragma unroll
    for (int k = 0; k < TOPK; ++k) {
        float bv = v; int bi = lane;
#pragma unroll
        for (int off = 16; off; off >>= 1) {
            float ov = __shfl_xor_sync(0xffffffffu, bv, off);
            int   oi = __shfl_xor_sync(0xffffffffu, bi, off);
            if (ov > bv || (ov == bv && oi < bi)) { bv = ov; bi = oi; }
        }
        float ws = __shfl_sync(0xffffffffu, s, bi);
        if (lane == k)  { sel_e = bi; sel_w = ws; }
        if (lane == bi) v = -INFINITY;
    }

    float wv = (lane < TOPK) ? sel_w : 0.f;
#pragma unroll
    for (int off = 16; off; off >>= 1) wv += __shfl_xor_sync(0xffffffffu, wv, off);
    if (lane < TOPK) {
        g_topk_ids[t * TOPK + lane] = sel_e;
        g_topk_w  [t * TOPK + lane] = sel_w / wv * RSF;
    }
}

// ---------------- capacity ranking ----------------
__global__ void rank_kernel() {
    int w    = threadIdx.x >> 5;
    int lane = threadIdx.x & 31;
    int cnt  = 0;
    for (int i0 = 0; i0 < T * TOPK; i0 += 32) {
        int i = i0 + lane;
        int e = g_topk_ids[i];
        bool m = (e == w);
        unsigned mask = __ballot_sync(0xffffffffu, m);
        if (m) {
            int r = cnt + __popc(mask & ((1u << lane) - 1u));
            if (r < CAP) {
                g_assign_slot[i] = w * CAP + r;
                g_slot_token[w * CAP + r] = i >> 3;
            } else {
                g_assign_slot[i] = -1;
            }
        }
        cnt += __popc(mask);
    }
    if (lane == 0) g_counts[w] = min(cnt, CAP);
}

// ============================================================================
// Fused gate/up tf32 GEMM: C = silu(A@Bg)*(A@Bu). Block M=128,N=64.
// 8 warps 4(m) x 2(n); warp tile 32x32. [row][k] layout, double-buffered,
// hoisted ldmatrix addresses.
// ============================================================================
template <bool GATHER, bool GROUPED, int AM, int CM>
__global__ void __launch_bounds__(256, 2)
gemm_fused(const float* __restrict__ Ain, int lda,
           const float* __restrict__ B, int ldb, int up_off, long long b_estride,
           float* __restrict__ Cin, int ldc, long long c_estride,
           int M, int Kd) {
    const float* A  = resolve<AM>(const_cast<float*>(Ain));
    float*       Cm = resolve<CM>(Cin);

    const int e    = GROUPED ? blockIdx.z : 0;
    const int Mloc = GROUPED ? g_counts[e] : M;
    const int m0   = blockIdx.y * 128;
    if (m0 >= Mloc) return;
    const int n0   = blockIdx.x * 64;

    const float* Bp = B + (GROUPED ? (long long)e * b_estride : 0ll);
    float*       Cp = Cm + (GROUPED ? (long long)e * c_estride : 0ll);

    __shared__ unsigned As[2][128][RS];
    __shared__ unsigned Bg[2][64][RS];
    __shared__ unsigned Bu[2][64][RS];
    const unsigned ABYTES = 128 * RS * 4;
    const unsigned BBYTES = 64 * RS * 4;

    const int tid  = threadIdx.x;
    const int lane = tid & 31;
    const int wid  = tid >> 5;
    const int gid  = lane >> 2;
    const int tig  = lane & 3;
    const int mt0  = (wid >> 1) * 2;
    const int nt0  = (wid & 1) * 4;

    // A staging
    const int r0 = tid >> 2;
    const int k4 = (tid & 3) * 4;
    const int gm0 = m0 + r0, gm1 = m0 + r0 + 64;
    const bool av0 = gm0 < Mloc, av1 = gm1 < Mloc;
    int row0, row1;
    if (GATHER) {
        row0 = av0 ? g_slot_token[e * CAP + gm0] : 0;
        row1 = av1 ? g_slot_token[e * CAP + gm1] : 0;
    } else {
        row0 = av0 ? gm0 : 0;
        row1 = av1 ? gm1 : 0;
    }
    const float* ap0 = A + (long long)row0 * lda + k4;
    const float* ap1 = A + (long long)row1 * lda + k4;

    // B staging: column bn, 8 k-rows from bkq; upper half of block does Bu
    const int bn  = tid & 63;
    const int bkq = ((tid >> 6) & 1) * 8;
    const bool isUp = (tid >> 7) != 0;
    const float* bp = Bp + n0 + bn + (isUp ? up_off : 0);
    unsigned* bdst0 = isUp ? &Bu[0][bn][bkq] : &Bg[0][bn][bkq];

    float accg[2][4][4], accu[2][4][4];
#pragma unroll
    for (int mi = 0; mi < 2; ++mi)
#pragma unroll
        for (int ni = 0; ni < 4; ++ni)
#pragma unroll
            for (int r = 0; r < 4; ++r) { accg[mi][ni][r] = 0.f; accu[mi][ni][r] = 0.f; }

    // hoisted ldmatrix addresses (stage 0)
    const int aRow = (lane & 15);
    const int aCol = (lane >> 4) * 4;
    const int bRow = (lane & 7) + ((lane >> 4) * 8);
    const int bCol = ((lane >> 3) & 1) * 4;
    unsigned aAddr[2], gAddr[2], uAddr[2];
#pragma unroll
    for (int mi = 0; mi < 2; ++mi)
        aAddr[mi] = (unsigned)__cvta_generic_to_shared(&As[0][0][0]) +
                    (((mt0 + mi) * 16 + aRow) * RS + aCol) * 4;
#pragma unroll
    for (int ni = 0; ni < 2; ++ni) {
        gAddr[ni] = (unsigned)__cvta_generic_to_shared(&Bg[0][0][0]) +
                    (((nt0 + 2 * ni) * 8 + bRow) * RS + bCol) * 4;
        uAddr[ni] = (unsigned)__cvta_generic_to_shared(&Bu[0][0][0]) +
                    (((nt0 + 2 * ni) * 8 + bRow) * RS + bCol) * 4;
    }

    const float4 fz = make_float4(0.f, 0.f, 0.f, 0.f);
    float4 ra0 = av0 ? *(const float4*)(ap0) : fz;
    float4 ra1 = av1 ? *(const float4*)(ap1) : fz;
    float rb[8];
#pragma unroll
    for (int i = 0; i < 8; ++i) rb[i] = bp[(long long)(bkq + i) * ldb];

    // prologue: fill stage 0
    *(uint4*)&As[0][r0][k4]      = cvt4(ra0);
    *(uint4*)&As[0][r0 + 64][k4] = cvt4(ra1);
#pragma unroll
    for (int i = 0; i < 8; ++i) bdst0[i] = f2tf(rb[i]);
    __syncthreads();

    for (int k0 = 0; k0 < Kd; k0 += 16) {
        const unsigned st = ((k0 >> 4) & 1);
        const unsigned aoff = st * ABYTES, boff = st * BBYTES;
        const bool nxt = (k0 + 16) < Kd;
        if (nxt) {
            ra0 = av0 ? *(const float4*)(ap0 + k0 + 16) : fz;
            ra1 = av1 ? *(const float4*)(ap1 + k0 + 16) : fz;
#pragma unroll
            for (int i = 0; i < 8; ++i) rb[i] = bp[(long long)(k0 + 16 + bkq + i) * ldb];
        }
#pragma unroll
        for (int kt = 0; kt < 2; ++kt) {
            const unsigned ko = kt * 32;   // 8 words
            uint4 af[2];
#pragma unroll
            for (int mi = 0; mi < 2; ++mi) af[mi] = ldsm4(aAddr[mi] + aoff + ko);
            uint4 bg0 = ldsm4(gAddr[0] + boff + ko);
            uint4 bg1 = ldsm4(gAddr[1] + boff + ko);
            uint4 bu0 = ldsm4(uAddr[0] + boff + ko);
            uint4 bu1 = ldsm4(uAddr[1] + boff + ko);
#pragma unroll
            for (int mi = 0; mi < 2; ++mi) {
                mma_tf32(accg[mi][0], af[mi], bg0.x, bg0.y);
                mma_tf32(accg[mi][1], af[mi], bg0.z, bg0.w);
                mma_tf32(accg[mi][2], af[mi], bg1.x, bg1.y);
                mma_tf32(accg[mi][3], af[mi], bg1.z, bg1.w);
                mma_tf32(accu[mi][0], af[mi], bu0.x, bu0.y);
                mma_tf32(accu[mi][1], af[mi], bu0.z, bu0.w);
                mma_tf32(accu[mi][2], af[mi], bu1.x, bu1.y);
                mma_tf32(accu[mi][3], af[mi], bu1.z, bu1.w);
            }
        }
        if (nxt) {
            const unsigned s2 = st ^ 1;
            *(uint4*)&As[s2][r0][k4]      = cvt4(ra0);
            *(uint4*)&As[s2][r0 + 64][k4] = cvt4(ra1);
            unsigned* bd = bdst0 + s2 * (BBYTES / 4);
#pragma unroll
            for (int i = 0; i < 8; ++i) bd[i] = f2tf(rb[i]);
        }
        __syncthreads();
    }

    // epilogue
#pragma unroll
    for (int mi = 0; mi < 2; ++mi) {
        int rA = m0 + (mt0 + mi) * 16 + gid;
        int rB = rA + 8;
#pragma unroll
        for (int ni = 0; ni < 4; ++ni) {
            int c0 = n0 + (nt0 + ni) * 8 + 2 * tig;
            if (rA < Mloc) {
                float2 v = make_float2(silu_mul(accg[mi][ni][0], accu[mi][ni][0]),
                                       silu_mul(accg[mi][ni][1], accu[mi][ni][1]));
                *(float2*)&Cp[(long long)rA * ldc + c0] = v;
            }
            if (rB < Mloc) {
                float2 v = make_float2(silu_mul(accg[mi][ni][2], accu[mi][ni][2]),
                                       silu_mul(accg[mi][ni][3], accu[mi][ni][3]));
                *(float2*)&Cp[(long long)rB * ldc + c0] = v;
            }
        }
    }
}

// ============================================================================
// Plain tf32 GEMM: C = A @ B. Block M=128,N=128. 8 warps 2(m) x 4(n);
// warp tile 64x32. [row][k] layout, double-buffered, hoisted addresses.
// ============================================================================
template <bool GROUPED, int AM, int CM>
__global__ void __launch_bounds__(256, 2)
gemm_plain(const float* __restrict__ Ain, int lda, long long a_estride,
           const float* __restrict__ B, int ldb, long long b_estride,
           float* __restrict__ Cin, int ldc, long long c_estride,
           int M, int Kd) {
    const float* A  = resolve<AM>(const_cast<float*>(Ain));
    float*       Cm = resolve<CM>(Cin);

    const int e    = GROUPED ? blockIdx.z : 0;
    const int Mloc = GROUPED ? g_counts[e] : M;
    const int m0   = blockIdx.y * 128;
    if (m0 >= Mloc) return;
    const int n0   = blockIdx.x * 128;

    const float* Bp = B + (GROUPED ? (long long)e * b_estride : 0ll);
    const float* Ap = A + (GROUPED ? (long long)e * a_estride : 0ll);
    float*       Cp = Cm + (GROUPED ? (long long)e * c_estride : 0ll);

    __shared__ unsigned As[2][128][RS];
    __shared__ unsigned Bs[2][128][RS];
    const unsigned TBYTES = 128 * RS * 4;

    const int tid  = threadIdx.x;
    const int lane = tid & 31;
    const int wid  = tid >> 5;
    const int gid  = lane >> 2;
    const int tig  = lane & 3;
    const int mt0  = (wid >> 2) * 4;
    const int nt0  = (wid & 3) * 4;

    const int r0 = tid >> 2;
    const int k4 = (tid & 3) * 4;
    const int gm0 = m0 + r0, gm1 = m0 + r0 + 64;
    const bool av0 = gm0 < Mloc, av1 = gm1 < Mloc;
    const float* ap0 = Ap + (long long)(av0 ? gm0 : 0) * lda + k4;
    const float* ap1 = Ap + (long long)(av1 ? gm1 : 0) * lda + k4;

    const int bn  = tid & 127;
    const int bkq = (tid >> 7) * 8;
    const float* bp = Bp + n0 + bn;
    unsigned* bdst0 = &Bs[0][bn][bkq];

    float acc[4][4][4];
#pragma unroll
    for (int mi = 0; mi < 4; ++mi)
#pragma unroll
        for (int ni = 0; ni < 4; ++ni)
#pragma unroll
            for (int r = 0; r < 4; ++r) acc[mi][ni][r] = 0.f;

    const int aRow = (lane & 15);
    const int aCol = (lane >> 4) * 4;
    const int bRow = (lane & 7) + ((lane >> 4) * 8);
    const int bCol = ((lane >> 3) & 1) * 4;
    unsigned aAddr[4], bAddr[2];
#pragma unroll
    for (int mi = 0; mi < 4; ++mi)
        aAddr[mi] = (unsigned)__cvta_generic_to_shared(&As[0][0][0]) +
                    (((mt0 + mi) * 16 + aRow) * RS + aCol) * 4;
#pragma unroll
    for (int ni = 0; ni < 2; ++ni)
        bAddr[ni] = (unsigned)__cvta_generic_to_shared(&Bs[0][0][0]) +
                    (((nt0 + 2 * ni) * 8 + bRow) * RS + bCol) * 4;

    const float4 fz = make_float4(0.f, 0.f, 0.f, 0.f);
    float4 ra0 = av0 ? *(const float4*)(ap0) : fz;
    float4 ra1 = av1 ? *(const float4*)(ap1) : fz;
    float rb[8];
#pragma unroll
    for (int i = 0; i < 8; ++i) rb[i] = bp[(long long)(bkq + i) * ldb];

    *(uint4*)&As[0][r0][k4]      = cvt4(ra0);
    *(uint4*)&As[0][r0 + 64][k4] = cvt4(ra1);
#pragma unroll
    for (int i = 0; i < 8; ++i) bdst0[i] = f2tf(rb[i]);
    __syncthreads();

    for (int k0 = 0; k0 < Kd; k0 += 16) {
        const unsigned st = ((k0 >> 4) & 1);
        const unsigned soff = st * TBYTES;
        const bool nxt = (k0 + 16) < Kd;
        if (nxt) {
            ra0 = av0 ? *(const float4*)(ap0 + k0 + 16) : fz;
            ra1 = av1 ? *(const float4*)(ap1 + k0 + 16) : fz;
#pragma unroll
            for (int i = 0; i < 8; ++i) rb[i] = bp[(long long)(k0 + 16 + bkq + i) * ldb];
        }
#pragma unroll
        for (int kt = 0; kt < 2; ++kt) {
            const unsigned ko = kt * 32;
            uint4 af[4];
#pragma unroll
            for (int mi = 0; mi < 4; ++mi) af[mi] = ldsm4(aAddr[mi] + soff + ko);
            uint4 b0 = ldsm4(bAddr[0] + soff + ko);
            uint4 b1 = ldsm4(bAddr[1] + soff + ko);
#pragma unroll
            for (int mi = 0; mi < 4; ++mi) {
                mma_tf32(acc[mi][0], af[mi], b0.x, b0.y);
                mma_tf32(acc[mi][1], af[mi], b0.z, b0.w);
                mma_tf32(acc[mi][2], af[mi], b1.x, b1.y);
                mma_tf32(acc[mi][3], af[mi], b1.z, b1.w);
            }
        }
        if (nxt) {
            const unsigned s2 = st ^ 1;
            *(uint4*)&As[s2][r0][k4]      = cvt4(ra0);
            *(uint4*)&As[s2][r0 + 64][k4] = cvt4(ra1);
            unsigned* bd = bdst0 + s2 * (TBYTES / 4);
#pragma unroll
            for (int i = 0; i < 8; ++i) bd[i] = f2tf(rb[i]);
        }
        __syncthreads();
    }

#pragma unroll
    for (int mi = 0; mi < 4; ++mi) {
        int rA = m0 + (mt0 + mi) * 16 + gid;
        int rB = rA + 8;
#pragma unroll
        for (int ni = 0; ni < 4; ++ni) {
            int c0 = n0 + (nt0 + ni) * 8 + 2 * tig;
            if (rA < Mloc)
                *(float2*)&Cp[(long long)rA * ldc + c0] =
                    make_float2(acc[mi][ni][0], acc[mi][ni][1]);
            if (rB < Mloc)
                *(float2*)&Cp[(long long)rB * ldc + c0] =
                    make_float2(acc[mi][ni][2], acc[mi][ni][3]);
        }
    }
}

// ---------------- combine ----------------
__global__ void combine_kernel(float* __restrict__ out) {
    int t = blockIdx.x;
    __shared__ int   sslot[TOPK];
    __shared__ float sw[TOPK];
    if (threadIdx.x < TOPK) {
        sslot[threadIdx.x] = g_assign_slot[t * TOPK + threadIdx.x];
        sw[threadIdx.x]    = g_topk_w[t * TOPK + threadIdx.x];
    }
    __syncthreads();
    for (int h = threadIdx.x; h < HDIM; h += 256) {
        float acc = out[(long long)t * HDIM + h];
#pragma unroll
        for (int k = 0; k < TOPK; ++k) {
            int sl = sslot[k];
            if (sl >= 0) acc += sw[k] * g_y[(long long)sl * HDIM + h];
        }
        out[(long long)t * HDIM + h] = acc;
    }
}

// ---------------- launch ----------------
extern "C" void kernel_launch(void* const* d_in, const int* in_sizes, int n_in,
                              void* d_out, int out_size) {
    const float* x     = (const float*)d_in[0];
    const float* gw    = (const float*)d_in[2];
    const float* bias  = (const float*)d_in[3];
    const float* w13   = (const float*)d_in[4];
    const float* w2    = (const float*)d_in[5];
    const float* sgu   = (const float*)d_in[6];
    const float* sdn   = (const float*)d_in[7];
    float* out = (float*)d_out;

    routing_kernel<<<T, 256>>>(x, gw, bias);
    rank_kernel<<<1, 1024>>>();
    gemm_fused<true, true, PTR_PARAM, PTR_H1><<<dim3(IDIM / 64, CAP / 128, NE), 256>>>(
        x, HDIM,
        w13, 2 * IDIM, IDIM, (long long)HDIM * 2 * IDIM,
        nullptr, IDIM, (long long)CAP * IDIM,
        CAP, HDIM);
    gemm_plain<true, PTR_H1, PTR_Y><<<dim3(HDIM / 128, CAP / 128, NE), 256>>>(
        nullptr, IDIM, (long long)CAP * IDIM,
        w2, HDIM, (long long)IDIM * HDIM,
        nullptr, HDIM, (long long)CAP * HDIM,
        CAP, IDIM);
    gemm_fused<false, false, PTR_PARAM, PTR_HS><<<dim3(ISH / 64, T / 128, 1), 256>>>(
        x, HDIM,
        sgu, 2 * ISH, ISH, 0ll,
        nullptr, ISH, 0ll,
        T, HDIM);
    gemm_plain<false, PTR_HS, PTR_PARAM><<<dim3(HDIM / 128, T / 128, 1), 256>>>(
        nullptr, ISH, 0ll,
        sdn, HDIM, 0ll,
        out, HDIM, 0ll,
        T, ISH);
    combine_kernel<<<T, 256>>>(out);
}

// round 7
// speedup vs baseline: 1.0234x; 1.0234x over previous
#include <cuda_runtime.h>
#include <math.h>
#include <stdint.h>

// Problem constants
#define T      512
#define HDIM   2048
#define NE     32
#define TOPK   8
#define IDIM   1408
#define NGRP   8
#define TKG    4
#define CAP    256
#define RSF    2.5f
#define ISH    2816

// SMEM row stride in words: 16 data + 4 pad
#define RS 20

// ---------------- device scratch ----------------
__device__ int   g_topk_ids[T * TOPK];
__device__ float g_topk_w[T * TOPK];
__device__ int   g_assign_slot[T * TOPK];
__device__ int   g_slot_token[NE * CAP];
__device__ int   g_counts[NE];
__device__ float g_h1[NE * CAP * IDIM];
__device__ float g_y [NE * CAP * HDIM];
__device__ float g_hs[T * ISH];

#define PTR_PARAM 0
#define PTR_H1    1
#define PTR_Y     2
#define PTR_HS    3

template <int M>
__device__ __forceinline__ float* resolve(float* p) {
    if constexpr (M == PTR_H1) return g_h1;
    else if constexpr (M == PTR_Y) return g_y;
    else if constexpr (M == PTR_HS) return g_hs;
    else return p;
}

// ---------------- helpers ----------------
__device__ __forceinline__ unsigned f2tf(float f) {
    unsigned r; asm("cvt.rna.tf32.f32 %0, %1;" : "=r"(r) : "f"(f)); return r;
}
__device__ __forceinline__ void mma_tf32(float* c, uint4 a, unsigned b0, unsigned b1) {
    asm("mma.sync.aligned.m16n8k8.row.col.f32.tf32.tf32.f32 "
        "{%0,%1,%2,%3},{%4,%5,%6,%7},{%8,%9},{%0,%1,%2,%3};"
        : "+f"(c[0]), "+f"(c[1]), "+f"(c[2]), "+f"(c[3])
        : "r"(a.x), "r"(a.y), "r"(a.z), "r"(a.w), "r"(b0), "r"(b1));
}
__device__ __forceinline__ uint4 ldsm4(unsigned addr) {
    uint4 r;
    asm volatile("ldmatrix.sync.aligned.m8n8.x4.shared.b16 {%0,%1,%2,%3}, [%4];"
                 : "=r"(r.x), "=r"(r.y), "=r"(r.z), "=r"(r.w) : "r"(addr));
    return r;
}
__device__ __forceinline__ float silu_mul(float g, float u) {
    return (g / (1.f + expf(-g))) * u;
}
__device__ __forceinline__ uint4 cvt4(float4 v) {
    return make_uint4(f2tf(v.x), f2tf(v.y), f2tf(v.z), f2tf(v.w));
}

// ---------------- routing ----------------
__global__ void routing_kernel(const float* __restrict__ x,
                               const float* __restrict__ gw,
                               const float* __restrict__ bias) {
    int t    = blockIdx.x;
    int tid  = threadIdx.x;
    int lane = tid & 31;
    int wid  = tid >> 5;

    __shared__ float part[8][32];
    const float* xr = x + (long long)t * HDIM;
    float acc = 0.f;
    int h0 = wid * (HDIM / 8);
    for (int h = h0; h < h0 + HDIM / 8; ++h)
        acc += xr[h] * gw[h * NE + lane];
    part[wid][lane] = acc;
    __syncthreads();

    if (wid != 0) return;

    float logit = 0.f;
#pragma unroll
    for (int w = 0; w < 8; ++w) logit += part[w][lane];

    float s  = 1.f / (1.f + expf(-logit));
    float sb = s + bias[lane];

    float p   = __shfl_xor_sync(0xffffffffu, sb, 1);
    float hi  = fmaxf(sb, p), lo = fminf(sb, p);
    float hi2 = __shfl_xor_sync(0xffffffffu, hi, 2);
    float lo2 = __shfl_xor_sync(0xffffffffu, lo, 2);
    float gs  = (hi >= hi2) ? hi + fmaxf(hi2, lo) : hi2 + fmaxf(hi, lo2);

    int g = lane >> 2;
    int grank = 0;
#pragma unroll
    for (int g2 = 0; g2 < NGRP; ++g2) {
        float og = __shfl_sync(0xffffffffu, gs, g2 * 4);
        if (og > gs || (og == gs && g2 < g)) ++grank;
    }
    float cand = (grank < TKG) ? sb : -INFINITY;

    float v = cand;
    int   sel_e = 0; float sel_w = 0.f;
#pragma unroll
    for (int k = 0; k < TOPK; ++k) {
        float bv = v; int bi = lane;
#pragma unroll
        for (int off = 16; off; off >>= 1) {
            float ov = __shfl_xor_sync(0xffffffffu, bv, off);
            int   oi = __shfl_xor_sync(0xffffffffu, bi, off);
            if (ov > bv || (ov == bv && oi < bi)) { bv = ov; bi = oi; }
        }
        float ws = __shfl_sync(0xffffffffu, s, bi);
        if (lane == k)  { sel_e = bi; sel_w = ws; }
        if (lane == bi) v = -INFINITY;
    }

    float wv = (lane < TOPK) ? sel_w : 0.f;
#pragma unroll
    for (int off = 16; off; off >>= 1) wv += __shfl_xor_sync(0xffffffffu, wv, off);
    if (lane < TOPK) {
        g_topk_ids[t * TOPK + lane] = sel_e;
        g_topk_w  [t * TOPK + lane] = sel_w / wv * RSF;
    }
}

// ---------------- capacity ranking ----------------
__global__ void rank_kernel() {
    int w    = threadIdx.x >> 5;
    int lane = threadIdx.x & 31;
    int cnt  = 0;
    for (int i0 = 0; i0 < T * TOPK; i0 += 32) {
        int i = i0 + lane;
        int e = g_topk_ids[i];
        bool m = (e == w);
        unsigned mask = __ballot_sync(0xffffffffu, m);
        if (m) {
            int r = cnt + __popc(mask & ((1u << lane) - 1u));
            if (r < CAP) {
                g_assign_slot[i] = w * CAP + r;
                g_slot_token[w * CAP + r] = i >> 3;
            } else {
                g_assign_slot[i] = -1;
            }
        }
        cnt += __popc(mask);
    }
    if (lane == 0) g_counts[w] = min(cnt, CAP);
}

// ============================================================================
// Fused gate/up tf32 GEMM: C = silu(A@Bg)*(A@Bu). Block M=128,N=64.
// 4 warps 2(m) x 2(n); warp tile 64 x 32(gate)+32(up). 128 threads.
// ============================================================================
template <bool GATHER, bool GROUPED, int AM, int CM>
__global__ void __launch_bounds__(128, 2)
gemm_fused(const float* __restrict__ Ain, int lda,
           const float* __restrict__ B, int ldb, int up_off, long long b_estride,
           float* __restrict__ Cin, int ldc, long long c_estride,
           int M, int Kd) {
    const float* A  = resolve<AM>(const_cast<float*>(Ain));
    float*       Cm = resolve<CM>(Cin);

    const int e    = GROUPED ? blockIdx.z : 0;
    const int Mloc = GROUPED ? g_counts[e] : M;
    const int m0   = blockIdx.y * 128;
    if (m0 >= Mloc) return;
    const int n0   = blockIdx.x * 64;

    const float* Bp = B + (GROUPED ? (long long)e * b_estride : 0ll);
    float*       Cp = Cm + (GROUPED ? (long long)e * c_estride : 0ll);

    __shared__ unsigned As[128][RS];
    __shared__ unsigned Bg[64][RS];
    __shared__ unsigned Bu[64][RS];

    const int tid  = threadIdx.x;
    const int lane = tid & 31;
    const int wid  = tid >> 5;            // 4 warps
    const int gid  = lane >> 2;
    const int tig  = lane & 3;
    const int mt0  = (wid >> 1) * 4;      // 4 m16 tiles per warp
    const int nt0  = (wid & 1) * 4;       // 4 n8 tiles per warp

    // A staging: 4 rows per thread (r0 + 32j), k-quad k4
    const int r0 = tid >> 2;              // 0..31
    const int k4 = (tid & 3) * 4;
    const float* ap[4];
    bool av[4];
#pragma unroll
    for (int j = 0; j < 4; ++j) {
        int gm = m0 + r0 + 32 * j;
        av[j] = gm < Mloc;
        int row;
        if (GATHER) row = av[j] ? g_slot_token[e * CAP + gm] : 0;
        else        row = av[j] ? gm : 0;
        ap[j] = A + (long long)row * lda + k4;
    }

    // B staging: thread -> one column (gate if tid<64 else up), 16 k's
    const int bn  = tid & 63;
    const bool isUp = tid >= 64;
    const float* bp = Bp + n0 + bn + (isUp ? up_off : 0);
    unsigned* bdst = isUp ? &Bu[bn][0] : &Bg[bn][0];

    float accg[4][4][4], accu[4][4][4];
#pragma unroll
    for (int mi = 0; mi < 4; ++mi)
#pragma unroll
        for (int ni = 0; ni < 4; ++ni)
#pragma unroll
            for (int r = 0; r < 4; ++r) { accg[mi][ni][r] = 0.f; accu[mi][ni][r] = 0.f; }

    // hoisted ldmatrix addresses
    const int aRow = (lane & 15);
    const int aCol = (lane >> 4) * 4;
    const int bRow = (lane & 7) + ((lane >> 4) * 8);
    const int bCol = ((lane >> 3) & 1) * 4;
    unsigned aAddr[4], gAddr[2], uAddr[2];
#pragma unroll
    for (int mi = 0; mi < 4; ++mi)
        aAddr[mi] = (unsigned)__cvta_generic_to_shared(&As[0][0]) +
                    (((mt0 + mi) * 16 + aRow) * RS + aCol) * 4;
#pragma unroll
    for (int nj = 0; nj < 2; ++nj) {
        gAddr[nj] = (unsigned)__cvta_generic_to_shared(&Bg[0][0]) +
                    (((nt0 + 2 * nj) * 8 + bRow) * RS + bCol) * 4;
        uAddr[nj] = (unsigned)__cvta_generic_to_shared(&Bu[0][0]) +
                    (((nt0 + 2 * nj) * 8 + bRow) * RS + bCol) * 4;
    }

    const float4 fz = make_float4(0.f, 0.f, 0.f, 0.f);
    float4 ra[4];
    float rb[16];
#pragma unroll
    for (int j = 0; j < 4; ++j) ra[j] = av[j] ? *(const float4*)(ap[j]) : fz;
#pragma unroll
    for (int i = 0; i < 16; ++i) rb[i] = bp[(long long)i * ldb];

    for (int k0 = 0; k0 < Kd; k0 += 16) {
        // stage
#pragma unroll
        for (int j = 0; j < 4; ++j)
            *(uint4*)&As[r0 + 32 * j][k4] = cvt4(ra[j]);
#pragma unroll
        for (int q = 0; q < 4; ++q)
            *(uint4*)&bdst[q * 4] = make_uint4(f2tf(rb[q*4]), f2tf(rb[q*4+1]),
                                               f2tf(rb[q*4+2]), f2tf(rb[q*4+3]));
        __syncthreads();

        const bool nxt = (k0 + 16) < Kd;
        if (nxt) {
#pragma unroll
            for (int j = 0; j < 4; ++j)
                ra[j] = av[j] ? *(const float4*)(ap[j] + k0 + 16) : fz;
#pragma unroll
            for (int i = 0; i < 16; ++i) rb[i] = bp[(long long)(k0 + 16 + i) * ldb];
        }

#pragma unroll
        for (int kt = 0; kt < 2; ++kt) {
            const unsigned ko = kt * 32;
            uint4 af[4];
#pragma unroll
            for (int mi = 0; mi < 4; ++mi) af[mi] = ldsm4(aAddr[mi] + ko);
            uint4 bg0 = ldsm4(gAddr[0] + ko);
            uint4 bg1 = ldsm4(gAddr[1] + ko);
            uint4 bu0 = ldsm4(uAddr[0] + ko);
            uint4 bu1 = ldsm4(uAddr[1] + ko);
#pragma unroll
            for (int mi = 0; mi < 4; ++mi) {
                mma_tf32(accg[mi][0], af[mi], bg0.x, bg0.y);
                mma_tf32(accg[mi][1], af[mi], bg0.z, bg0.w);
                mma_tf32(accg[mi][2], af[mi], bg1.x, bg1.y);
                mma_tf32(accg[mi][3], af[mi], bg1.z, bg1.w);
                mma_tf32(accu[mi][0], af[mi], bu0.x, bu0.y);
                mma_tf32(accu[mi][1], af[mi], bu0.z, bu0.w);
                mma_tf32(accu[mi][2], af[mi], bu1.x, bu1.y);
                mma_tf32(accu[mi][3], af[mi], bu1.z, bu1.w);
            }
        }
        __syncthreads();
    }

    // epilogue
#pragma unroll
    for (int mi = 0; mi < 4; ++mi) {
        int rA = m0 + (mt0 + mi) * 16 + gid;
        int rB = rA + 8;
#pragma unroll
        for (int ni = 0; ni < 4; ++ni) {
            int c0 = n0 + (nt0 + ni) * 8 + 2 * tig;
            if (rA < Mloc) {
                float2 v = make_float2(silu_mul(accg[mi][ni][0], accu[mi][ni][0]),
                                       silu_mul(accg[mi][ni][1], accu[mi][ni][1]));
                *(float2*)&Cp[(long long)rA * ldc + c0] = v;
            }
            if (rB < Mloc) {
                float2 v = make_float2(silu_mul(accg[mi][ni][2], accu[mi][ni][2]),
                                       silu_mul(accg[mi][ni][3], accu[mi][ni][3]));
                *(float2*)&Cp[(long long)rB * ldc + c0] = v;
            }
        }
    }
}

// ============================================================================
// Plain tf32 GEMM: C = A @ B. Block M=128,N=128. 4 warps 2(m) x 2(n);
// warp tile 64x64. 128 threads.
// ============================================================================
template <bool GROUPED, int AM, int CM>
__global__ void __launch_bounds__(128, 2)
gemm_plain(const float* __restrict__ Ain, int lda, long long a_estride,
           const float* __restrict__ B, int ldb, long long b_estride,
           float* __restrict__ Cin, int ldc, long long c_estride,
           int M, int Kd) {
    const float* A  = resolve<AM>(const_cast<float*>(Ain));
    float*       Cm = resolve<CM>(Cin);

    const int e    = GROUPED ? blockIdx.z : 0;
    const int Mloc = GROUPED ? g_counts[e] : M;
    const int m0   = blockIdx.y * 128;
    if (m0 >= Mloc) return;
    const int n0   = blockIdx.x * 128;

    const float* Bp = B + (GROUPED ? (long long)e * b_estride : 0ll);
    const float* Ap = A + (GROUPED ? (long long)e * a_estride : 0ll);
    float*       Cp = Cm + (GROUPED ? (long long)e * c_estride : 0ll);

    __shared__ unsigned As[128][RS];
    __shared__ unsigned Bs[128][RS];

    const int tid  = threadIdx.x;
    const int lane = tid & 31;
    const int wid  = tid >> 5;
    const int gid  = lane >> 2;
    const int tig  = lane & 3;
    const int mt0  = (wid >> 1) * 4;      // 4 m16 tiles
    const int nt0  = (wid & 1) * 8;       // 8 n8 tiles

    const int r0 = tid >> 2;
    const int k4 = (tid & 3) * 4;
    const float* ap[4];
    bool av[4];
#pragma unroll
    for (int j = 0; j < 4; ++j) {
        int gm = m0 + r0 + 32 * j;
        av[j] = gm < Mloc;
        ap[j] = Ap + (long long)(av[j] ? gm : 0) * lda + k4;
    }

    const int bn = tid;                    // one column per thread (0..127)
    const float* bp = Bp + n0 + bn;

    float acc[4][8][4];
#pragma unroll
    for (int mi = 0; mi < 4; ++mi)
#pragma unroll
        for (int ni = 0; ni < 8; ++ni)
#pragma unroll
            for (int r = 0; r < 4; ++r) acc[mi][ni][r] = 0.f;

    const int aRow = (lane & 15);
    const int aCol = (lane >> 4) * 4;
    const int bRow = (lane & 7) + ((lane >> 4) * 8);
    const int bCol = ((lane >> 3) & 1) * 4;
    unsigned aAddr[4], bAddr[4];
#pragma unroll
    for (int mi = 0; mi < 4; ++mi)
        aAddr[mi] = (unsigned)__cvta_generic_to_shared(&As[0][0]) +
                    (((mt0 + mi) * 16 + aRow) * RS + aCol) * 4;
#pragma unroll
    for (int nj = 0; nj < 4; ++nj)
        bAddr[nj] = (unsigned)__cvta_generic_to_shared(&Bs[0][0]) +
                    (((nt0 + 2 * nj) * 8 + bRow) * RS + bCol) * 4;

    const float4 fz = make_float4(0.f, 0.f, 0.f, 0.f);
    float4 ra[4];
    float rb[16];
#pragma unroll
    for (int j = 0; j < 4; ++j) ra[j] = av[j] ? *(const float4*)(ap[j]) : fz;
#pragma unroll
    for (int i = 0; i < 16; ++i) rb[i] = bp[(long long)i * ldb];

    for (int k0 = 0; k0 < Kd; k0 += 16) {
#pragma unroll
        for (int j = 0; j < 4; ++j)
            *(uint4*)&As[r0 + 32 * j][k4] = cvt4(ra[j]);
#pragma unroll
        for (int q = 0; q < 4; ++q)
            *(uint4*)&Bs[bn][q * 4] = make_uint4(f2tf(rb[q*4]), f2tf(rb[q*4+1]),
                                                 f2tf(rb[q*4+2]), f2tf(rb[q*4+3]));
        __syncthreads();

        const bool nxt = (k0 + 16) < Kd;
        if (nxt) {
#pragma unroll
            for (int j = 0; j < 4; ++j)
                ra[j] = av[j] ? *(const float4*)(ap[j] + k0 + 16) : fz;
#pragma unroll
            for (int i = 0; i < 16; ++i) rb[i] = bp[(long long)(k0 + 16 + i) * ldb];
        }

#pragma unroll
        for (int kt = 0; kt < 2; ++kt) {
            const unsigned ko = kt * 32;
            uint4 af[4], bf[4];
#pragma unroll
            for (int mi = 0; mi < 4; ++mi) af[mi] = ldsm4(aAddr[mi] + ko);
#pragma unroll
            for (int nj = 0; nj < 4; ++nj) bf[nj] = ldsm4(bAddr[nj] + ko);
#pragma unroll
            for (int mi = 0; mi < 4; ++mi)
#pragma unroll
                for (int nj = 0; nj < 4; ++nj) {
                    mma_tf32(acc[mi][2 * nj],     af[mi], bf[nj].x, bf[nj].y);
                    mma_tf32(acc[mi][2 * nj + 1], af[mi], bf[nj].z, bf[nj].w);
                }
        }
        __syncthreads();
    }

#pragma unroll
    for (int mi = 0; mi < 4; ++mi) {
        int rA = m0 + (mt0 + mi) * 16 + gid;
        int rB = rA + 8;
#pragma unroll
        for (int ni = 0; ni < 8; ++ni) {
            int c0 = n0 + (nt0 + ni) * 8 + 2 * tig;
            if (rA < Mloc)
                *(float2*)&Cp[(long long)rA * ldc + c0] =
                    make_float2(acc[mi][ni][0], acc[mi][ni][1]);
            if (rB < Mloc)
                *(float2*)&Cp[(long long)rB * ldc + c0] =
                    make_float2(acc[mi][ni][2], acc[mi][ni][3]);
        }
    }
}

// ---------------- combine ----------------
__global__ void combine_kernel(float* __restrict__ out) {
    int t = blockIdx.x;
    __shared__ int   sslot[TOPK];
    __shared__ float sw[TOPK];
    if (threadIdx.x < TOPK) {
        sslot[threadIdx.x] = g_assign_slot[t * TOPK + threadIdx.x];
        sw[threadIdx.x]    = g_topk_w[t * TOPK + threadIdx.x];
    }
    __syncthreads();
    for (int h = threadIdx.x; h < HDIM; h += 256) {
        float acc = out[(long long)t * HDIM + h];
#pragma unroll
        for (int k = 0; k < TOPK; ++k) {
            int sl = sslot[k];
            if (sl >= 0) acc += sw[k] * g_y[(long long)sl * HDIM + h];
        }
        out[(long long)t * HDIM + h] = acc;
    }
}

// ---------------- launch ----------------
extern "C" void kernel_launch(void* const* d_in, const int* in_sizes, int n_in,
                              void* d_out, int out_size) {
    const float* x     = (const float*)d_in[0];
    const float* gw    = (const float*)d_in[2];
    const float* bias  = (const float*)d_in[3];
    const float* w13   = (const float*)d_in[4];
    const float* w2    = (const float*)d_in[5];
    const float* sgu   = (const float*)d_in[6];
    const float* sdn   = (const float*)d_in[7];
    float* out = (float*)d_out;

    routing_kernel<<<T, 256>>>(x, gw, bias);
    rank_kernel<<<1, 1024>>>();
    gemm_fused<true, true, PTR_PARAM, PTR_H1><<<dim3(IDIM / 64, CAP / 128, NE), 128>>>(
        x, HDIM,
        w13, 2 * IDIM, IDIM, (long long)HDIM * 2 * IDIM,
        nullptr, IDIM, (long long)CAP * IDIM,
        CAP, HDIM);
    gemm_plain<true, PTR_H1, PTR_Y><<<dim3(HDIM / 128, CAP / 128, NE), 128>>>(
        nullptr, IDIM, (long long)CAP * IDIM,
        w2, HDIM, (long long)IDIM * HDIM,
        nullptr, HDIM, (long long)CAP * HDIM,
        CAP, IDIM);
    gemm_fused<false, false, PTR_PARAM, PTR_HS><<<dim3(ISH / 64, T / 128, 1), 128>>>(
        x, HDIM,
        sgu, 2 * ISH, ISH, 0ll,
        nullptr, ISH, 0ll,
        T, HDIM);
    gemm_plain<false, PTR_HS, PTR_PARAM><<<dim3(HDIM / 128, T / 128, 1), 128>>>(
        nullptr, ISH, 0ll,
        sdn, HDIM, 0ll,
        out, HDIM, 0ll,
        T, ISH);
    combine_kernel<<<T, 256>>>(out);
}

// round 9
// speedup vs baseline: 1.0598x; 1.0356x over previous
#include <cuda_runtime.h>
#include <math.h>
#include <stdint.h>

// Problem constants
#define T      512
#define HDIM   2048
#define NE     32
#define TOPK   8
#define IDIM   1408
#define NGRP   8
#define TKG    4
#define CAP    256
#define RSF    2.5f
#define ISH    2816

// SMEM geometry: k32 tiles, row stride 36 words (144B: 16B aligned, conflict-free)
#define RSW   36
#define A_STG (128 * RSW * 4)          // 18432 B per stage
#define B_STG (128 * RSW * 4)          // plain B stage
#define BG_STG (64 * RSW * 4)          // fused gate/up stage (9216)
#define SMEM_SZ (2 * A_STG + 2 * B_STG)   // 73728

// ---------------- device scratch ----------------
__device__ int   g_topk_ids[T * TOPK];
__device__ float g_topk_w[T * TOPK];
__device__ int   g_assign_slot[T * TOPK];
__device__ int   g_slot_token[NE * CAP];
__device__ int   g_counts[NE];
__device__ float g_xr[T * HDIM];           // tf32-rounded x
__device__ float g_h1[NE * CAP * IDIM];    // rounded silu*up
__device__ float g_y [NE * CAP * HDIM];
__device__ float g_hs[T * ISH];            // rounded shared silu*up

#define PTR_PARAM 0
#define PTR_H1    1
#define PTR_Y     2
#define PTR_HS    3
#define PTR_XR    4

template <int M>
__device__ __forceinline__ float* resolve(float* p) {
    if constexpr (M == PTR_H1) return g_h1;
    else if constexpr (M == PTR_Y) return g_y;
    else if constexpr (M == PTR_HS) return g_hs;
    else if constexpr (M == PTR_XR) return g_xr;
    else return p;
}

// ---------------- helpers ----------------
__device__ __forceinline__ unsigned f2tf(float f) {
    unsigned r; asm("cvt.rna.tf32.f32 %0, %1;" : "=r"(r) : "f"(f)); return r;
}
__device__ __forceinline__ uint4 cvt4(float4 v) {
    return make_uint4(f2tf(v.x), f2tf(v.y), f2tf(v.z), f2tf(v.w));
}
__device__ __forceinline__ void mma_tf32(float* c, uint4 a, unsigned b0, unsigned b1) {
    asm("mma.sync.aligned.m16n8k8.row.col.f32.tf32.tf32.f32 "
        "{%0,%1,%2,%3},{%4,%5,%6,%7},{%8,%9},{%0,%1,%2,%3};"
        : "+f"(c[0]), "+f"(c[1]), "+f"(c[2]), "+f"(c[3])
        : "r"(a.x), "r"(a.y), "r"(a.z), "r"(a.w), "r"(b0), "r"(b1));
}
__device__ __forceinline__ uint4 ldsm4(unsigned addr) {
    uint4 r;
    asm volatile("ldmatrix.sync.aligned.m8n8.x4.shared.b16 {%0,%1,%2,%3}, [%4];"
                 : "=r"(r.x), "=r"(r.y), "=r"(r.z), "=r"(r.w) : "r"(addr));
    return r;
}
__device__ __forceinline__ float silu_mul(float g, float u) {
    return (g / (1.f + expf(-g))) * u;
}
__device__ __forceinline__ void cpa16(unsigned dst, const float* src, unsigned n) {
    asm volatile("cp.async.cg.shared.global [%0], [%1], 16, %2;"
                 :: "r"(dst), "l"(src), "r"(n) : "memory");
}
#define CP_COMMIT() asm volatile("cp.async.commit_group;" ::: "memory")
#define CP_WAIT0()  asm volatile("cp.async.wait_group 0;" ::: "memory")

// ---------------- round x ----------------
__global__ void round_x_kernel(const float* __restrict__ x) {
    int i = blockIdx.x * 256 + threadIdx.x;
    float4 v = ((const float4*)x)[i];
    ((uint4*)g_xr)[i] = cvt4(v);
}

// ---------------- routing ----------------
__global__ void routing_kernel(const float* __restrict__ x,
                               const float* __restrict__ gw,
                               const float* __restrict__ bias) {
    int t    = blockIdx.x;
    int tid  = threadIdx.x;
    int lane = tid & 31;
    int wid  = tid >> 5;

    __shared__ float part[8][32];
    const float* xr = x + (long long)t * HDIM;
    float acc = 0.f;
    int h0 = wid * (HDIM / 8);
    for (int h = h0; h < h0 + HDIM / 8; ++h)
        acc += xr[h] * gw[h * NE + lane];
    part[wid][lane] = acc;
    __syncthreads();

    if (wid != 0) return;

    float logit = 0.f;
#pragma unroll
    for (int w = 0; w < 8; ++w) logit += part[w][lane];

    float s  = 1.f / (1.f + expf(-logit));
    float sb = s + bias[lane];

    float p   = __shfl_xor_sync(0xffffffffu, sb, 1);
    float hi  = fmaxf(sb, p), lo = fminf(sb, p);
    float hi2 = __shfl_xor_sync(0xffffffffu, hi, 2);
    float lo2 = __shfl_xor_sync(0xffffffffu, lo, 2);
    float gs  = (hi >= hi2) ? hi + fmaxf(hi2, lo) : hi2 + fmaxf(hi, lo2);

    int g = lane >> 2;
    int grank = 0;
#pragma unroll
    for (int g2 = 0; g2 < NGRP; ++g2) {
        float og = __shfl_sync(0xffffffffu, gs, g2 * 4);
        if (og > gs || (og == gs && g2 < g)) ++grank;
    }
    float cand = (grank < TKG) ? sb : -INFINITY;

    float v = cand;
    int   sel_e = 0; float sel_w = 0.f;
#pragma unroll
    for (int k = 0; k < TOPK; ++k) {
        float bv = v; int bi = lane;
#pragma unroll
        for (int off = 16; off; off >>= 1) {
            float ov = __shfl_xor_sync(0xffffffffu, bv, off);
            int   oi = __shfl_xor_sync(0xffffffffu, bi, off);
            if (ov > bv || (ov == bv && oi < bi)) { bv = ov; bi = oi; }
        }
        float ws = __shfl_sync(0xffffffffu, s, bi);
        if (lane == k)  { sel_e = bi; sel_w = ws; }
        if (lane == bi) v = -INFINITY;
    }

    float wv = (lane < TOPK) ? sel_w : 0.f;
#pragma unroll
    for (int off = 16; off; off >>= 1) wv += __shfl_xor_sync(0xffffffffu, wv, off);
    if (lane < TOPK) {
        g_topk_ids[t * TOPK + lane] = sel_e;
        g_topk_w  [t * TOPK + lane] = sel_w / wv * RSF;
    }
}

// ---------------- capacity ranking ----------------
__global__ void rank_kernel() {
    int w    = threadIdx.x >> 5;
    int lane = threadIdx.x & 31;
    int cnt  = 0;
    for (int i0 = 0; i0 < T * TOPK; i0 += 32) {
        int i = i0 + lane;
        int e = g_topk_ids[i];
        bool m = (e == w);
        unsigned mask = __ballot_sync(0xffffffffu, m);
        if (m) {
            int r = cnt + __popc(mask & ((1u << lane) - 1u));
            if (r < CAP) {
                g_assign_slot[i] = w * CAP + r;
                g_slot_token[w * CAP + r] = i >> 3;
            } else {
                g_assign_slot[i] = -1;
            }
        }
        cnt += __popc(mask);
    }
    if (lane == 0) g_counts[w] = min(cnt, CAP);
}

// ============================================================================
// Fused gate/up tf32 GEMM: C = silu(A@Bg)*(A@Bu), rounded to tf32 on store.
// Block M=128, N=64. 8 warps 4(m) x 2(n); warp tile 32x32(g)+32x32(u).
// A via cp.async (pre-rounded source), B via LDG+cvt+STS. k32 double-buffered.
// ============================================================================
template <bool GATHER, bool GROUPED, int AM, int CM>
__global__ void __launch_bounds__(256, 2)
gemm_fused(const float* __restrict__ Ain, int lda,
           const float* __restrict__ B, int ldb, int up_off, long long b_estride,
           float* __restrict__ Cin, int ldc, long long c_estride,
           int M, int Kd) {
    extern __shared__ char smem[];
    const float* A  = resolve<AM>(const_cast<float*>(Ain));
    float*       Cm = resolve<CM>(Cin);

    const int e    = GROUPED ? blockIdx.z : 0;
    const int Mloc = GROUPED ? g_counts[e] : M;
    const int m0   = blockIdx.y * 128;
    if (m0 >= Mloc) return;
    const int n0   = blockIdx.x * 64;

    const float* Bp = B + (GROUPED ? (long long)e * b_estride : 0ll);
    float*       Cp = Cm + (GROUPED ? (long long)e * c_estride : 0ll);

    const unsigned smb = (unsigned)__cvta_generic_to_shared(smem);
    const int tid  = threadIdx.x;
    const int lane = tid & 31;
    const int wid  = tid >> 5;
    const int gid  = lane >> 2;
    const int tig  = lane & 3;
    const int mt0  = (wid >> 1) * 2;
    const int nt0  = (wid & 1) * 4;

    // A cp.async map: row = tid>>1, k-half = (tid&1)*16
    const int arow = tid >> 1;
    const int akh  = (tid & 1) * 16;
    const int gm   = m0 + arow;
    const bool avl = gm < Mloc;
    int grow;
    if (GATHER) grow = avl ? g_slot_token[e * CAP + gm] : 0;
    else        grow = avl ? gm : 0;
    const float* asrc = A + (long long)grow * lda + akh;
    const unsigned adst = smb + (unsigned)arow * 144u + (unsigned)akh * 4u;
    const unsigned asz  = avl ? 16u : 0u;

    // B map: bn = tid&63 column, kh = ((tid>>6)&1)*16, isUp = tid>>7
    const int bn   = tid & 63;
    const int bkh  = ((tid >> 6) & 1) * 16;
    const bool isUp = (tid >> 7) != 0;
    const float* bp = Bp + n0 + bn + (isUp ? up_off : 0);
    const unsigned bReg0 = 2u * A_STG + (isUp ? 2u * BG_STG : 0u);
    unsigned* bdst0 = (unsigned*)(smem + bReg0) + bn * RSW + bkh;

    float accg[2][4][4], accu[2][4][4];
#pragma unroll
    for (int mi = 0; mi < 2; ++mi)
#pragma unroll
        for (int ni = 0; ni < 4; ++ni)
#pragma unroll
            for (int r = 0; r < 4; ++r) { accg[mi][ni][r] = 0.f; accu[mi][ni][r] = 0.f; }

    // ldmatrix addresses (stage 0)
    const int aRow = (lane & 15);
    const int aCol = (lane >> 4) * 4;
    const int bRow = (lane & 7) + ((lane >> 4) * 8);
    const int bCol = ((lane >> 3) & 1) * 4;
    unsigned aAddr[2], gAddr[2], uAddr[2];
#pragma unroll
    for (int mi = 0; mi < 2; ++mi)
        aAddr[mi] = smb + (((mt0 + mi) * 16 + aRow) * RSW + aCol) * 4;
#pragma unroll
    for (int nj = 0; nj < 2; ++nj) {
        gAddr[nj] = smb + 2u * A_STG +
                    (((nt0 + 2 * nj) * 8 + bRow) * RSW + bCol) * 4;
        uAddr[nj] = gAddr[nj] + 2u * BG_STG;
    }

    const int S = Kd / 32;
    float rb[16];

    // prologue: stage 0
#pragma unroll
    for (int q = 0; q < 4; ++q) cpa16(adst + q * 16, asrc + q * 4, asz);
    CP_COMMIT();
#pragma unroll
    for (int i = 0; i < 16; ++i) rb[i] = bp[(long long)(bkh + i) * ldb];
    CP_WAIT0();
#pragma unroll
    for (int q = 0; q < 4; ++q)
        *(uint4*)&bdst0[q * 4] = make_uint4(f2tf(rb[q*4]), f2tf(rb[q*4+1]),
                                            f2tf(rb[q*4+2]), f2tf(rb[q*4+3]));
    __syncthreads();

    for (int s = 0; s < S; ++s) {
        const unsigned buf = s & 1;
        const bool nxt = (s + 1) < S;
        if (nxt) {
            const unsigned b2 = buf ^ 1;
            const float* src = asrc + (s + 1) * 32;
#pragma unroll
            for (int q = 0; q < 4; ++q)
                cpa16(adst + b2 * A_STG + q * 16, src + q * 4, asz);
            CP_COMMIT();
#pragma unroll
            for (int i = 0; i < 16; ++i)
                rb[i] = bp[(long long)((s + 1) * 32 + bkh + i) * ldb];
        }
        const unsigned ao = buf * A_STG, bo = buf * BG_STG;
#pragma unroll
        for (int ks = 0; ks < 4; ++ks) {
            const unsigned ko = ks * 32;
            uint4 af[2];
#pragma unroll
            for (int mi = 0; mi < 2; ++mi) af[mi] = ldsm4(aAddr[mi] + ao + ko);
            uint4 bg0 = ldsm4(gAddr[0] + bo + ko);
            uint4 bg1 = ldsm4(gAddr[1] + bo + ko);
            uint4 bu0 = ldsm4(uAddr[0] + bo + ko);
            uint4 bu1 = ldsm4(uAddr[1] + bo + ko);
#pragma unroll
            for (int mi = 0; mi < 2; ++mi) {
                mma_tf32(accg[mi][0], af[mi], bg0.x, bg0.y);
                mma_tf32(accg[mi][1], af[mi], bg0.z, bg0.w);
                mma_tf32(accg[mi][2], af[mi], bg1.x, bg1.y);
                mma_tf32(accg[mi][3], af[mi], bg1.z, bg1.w);
                mma_tf32(accu[mi][0], af[mi], bu0.x, bu0.y);
                mma_tf32(accu[mi][1], af[mi], bu0.z, bu0.w);
                mma_tf32(accu[mi][2], af[mi], bu1.x, bu1.y);
                mma_tf32(accu[mi][3], af[mi], bu1.z, bu1.w);
            }
        }
        if (nxt) {
            unsigned* bd = bdst0 + (buf ^ 1) * (BG_STG / 4);
#pragma unroll
            for (int q = 0; q < 4; ++q)
                *(uint4*)&bd[q * 4] = make_uint4(f2tf(rb[q*4]), f2tf(rb[q*4+1]),
                                                 f2tf(rb[q*4+2]), f2tf(rb[q*4+3]));
            CP_WAIT0();
        }
        __syncthreads();
    }

    // epilogue: silu(g)*u, rounded to tf32 (consumed as GEMM A later)
#pragma unroll
    for (int mi = 0; mi < 2; ++mi) {
        int rA = m0 + (mt0 + mi) * 16 + gid;
        int rB = rA + 8;
#pragma unroll
        for (int ni = 0; ni < 4; ++ni) {
            int c0 = n0 + (nt0 + ni) * 8 + 2 * tig;
            if (rA < Mloc) {
                uint2 v = make_uint2(f2tf(silu_mul(accg[mi][ni][0], accu[mi][ni][0])),
                                     f2tf(silu_mul(accg[mi][ni][1], accu[mi][ni][1])));
                *(uint2*)&Cp[(long long)rA * ldc + c0] = v;
            }
            if (rB < Mloc) {
                uint2 v = make_uint2(f2tf(silu_mul(accg[mi][ni][2], accu[mi][ni][2])),
                                     f2tf(silu_mul(accg[mi][ni][3], accu[mi][ni][3])));
                *(uint2*)&Cp[(long long)rB * ldc + c0] = v;
            }
        }
    }
}

// ============================================================================
// Plain tf32 GEMM: C = A @ B. Block M=128,N=128. 8 warps 2(m) x 4(n);
// warp tile 64x32. A via cp.async (pre-rounded), B via LDG+cvt+STS. k32 x2buf.
// ============================================================================
template <bool GROUPED, int AM, int CM>
__global__ void __launch_bounds__(256, 2)
gemm_plain(const float* __restrict__ Ain, int lda, long long a_estride,
           const float* __restrict__ B, int ldb, long long b_estride,
           float* __restrict__ Cin, int ldc, long long c_estride,
           int M, int Kd) {
    extern __shared__ char smem[];
    const float* A  = resolve<AM>(const_cast<float*>(Ain));
    float*       Cm = resolve<CM>(Cin);

    const int e    = GROUPED ? blockIdx.z : 0;
    const int Mloc = GROUPED ? g_counts[e] : M;
    const int m0   = blockIdx.y * 128;
    if (m0 >= Mloc) return;
    const int n0   = blockIdx.x * 128;

    const float* Bp = B + (GROUPED ? (long long)e * b_estride : 0ll);
    const float* Ap = A + (GROUPED ? (long long)e * a_estride : 0ll);
    float*       Cp = Cm + (GROUPED ? (long long)e * c_estride : 0ll);

    const unsigned smb = (unsigned)__cvta_generic_to_shared(smem);
    const int tid  = threadIdx.x;
    const int lane = tid & 31;
    const int wid  = tid >> 5;
    const int gid  = lane >> 2;
    const int tig  = lane & 3;
    const int mt0  = (wid >> 2) * 4;
    const int nt0  = (wid & 3) * 4;

    const int arow = tid >> 1;
    const int akh  = (tid & 1) * 16;
    const int gm   = m0 + arow;
    const bool avl = gm < Mloc;
    const float* asrc = Ap + (long long)(avl ? gm : 0) * lda + akh;
    const unsigned adst = smb + (unsigned)arow * 144u + (unsigned)akh * 4u;
    const unsigned asz  = avl ? 16u : 0u;

    const int bn  = tid & 127;
    const int bkh = (tid >> 7) * 16;
    const float* bp = Bp + n0 + bn;
    unsigned* bdst0 = (unsigned*)(smem + 2u * A_STG) + bn * RSW + bkh;

    float acc[4][4][4];
#pragma unroll
    for (int mi = 0; mi < 4; ++mi)
#pragma unroll
        for (int ni = 0; ni < 4; ++ni)
#pragma unroll
            for (int r = 0; r < 4; ++r) acc[mi][ni][r] = 0.f;

    const int aRow = (lane & 15);
    const int aCol = (lane >> 4) * 4;
    const int bRow = (lane & 7) + ((lane >> 4) * 8);
    const int bCol = ((lane >> 3) & 1) * 4;
    unsigned aAddr[4], bAddr[2];
#pragma unroll
    for (int mi = 0; mi < 4; ++mi)
        aAddr[mi] = smb + (((mt0 + mi) * 16 + aRow) * RSW + aCol) * 4;
#pragma unroll
    for (int nj = 0; nj < 2; ++nj)
        bAddr[nj] = smb + 2u * A_STG +
                    (((nt0 + 2 * nj) * 8 + bRow) * RSW + bCol) * 4;

    const int S = Kd / 32;
    float rb[16];

#pragma unroll
    for (int q = 0; q < 4; ++q) cpa16(adst + q * 16, asrc + q * 4, asz);
    CP_COMMIT();
#pragma unroll
    for (int i = 0; i < 16; ++i) rb[i] = bp[(long long)(bkh + i) * ldb];
    CP_WAIT0();
#pragma unroll
    for (int q = 0; q < 4; ++q)
        *(uint4*)&bdst0[q * 4] = make_uint4(f2tf(rb[q*4]), f2tf(rb[q*4+1]),
                                            f2tf(rb[q*4+2]), f2tf(rb[q*4+3]));
    __syncthreads();

    for (int s = 0; s < S; ++s) {
        const unsigned buf = s & 1;
        const bool nxt = (s + 1) < S;
        if (nxt) {
            const unsigned b2 = buf ^ 1;
            const float* src = asrc + (s + 1) * 32;
#pragma unroll
            for (int q = 0; q < 4; ++q)
                cpa16(adst + b2 * A_STG + q * 16, src + q * 4, asz);
            CP_COMMIT();
#pragma unroll
            for (int i = 0; i < 16; ++i)
                rb[i] = bp[(long long)((s + 1) * 32 + bkh + i) * ldb];
        }
        const unsigned ao = buf * A_STG, bo = buf * B_STG;
#pragma unroll
        for (int ks = 0; ks < 4; ++ks) {
            const unsigned ko = ks * 32;
            uint4 af[4];
#pragma unroll
            for (int mi = 0; mi < 4; ++mi) af[mi] = ldsm4(aAddr[mi] + ao + ko);
            uint4 b0 = ldsm4(bAddr[0] + bo + ko);
            uint4 b1 = ldsm4(bAddr[1] + bo + ko);
#pragma unroll
            for (int mi = 0; mi < 4; ++mi) {
                mma_tf32(acc[mi][0], af[mi], b0.x, b0.y);
                mma_tf32(acc[mi][1], af[mi], b0.z, b0.w);
                mma_tf32(acc[mi][2], af[mi], b1.x, b1.y);
                mma_tf32(acc[mi][3], af[mi], b1.z, b1.w);
            }
        }
        if (nxt) {
            unsigned* bd = bdst0 + (buf ^ 1) * (B_STG / 4);
#pragma unroll
            for (int q = 0; q < 4; ++q)
                *(uint4*)&bd[q * 4] = make_uint4(f2tf(rb[q*4]), f2tf(rb[q*4+1]),
                                                 f2tf(rb[q*4+2]), f2tf(rb[q*4+3]));
            CP_WAIT0();
        }
        __syncthreads();
    }

#pragma unroll
    for (int mi = 0; mi < 4; ++mi) {
        int rA = m0 + (mt0 + mi) * 16 + gid;
        int rB = rA + 8;
#pragma unroll
        for (int ni = 0; ni < 4; ++ni) {
            int c0 = n0 + (nt0 + ni) * 8 + 2 * tig;
            if (rA < Mloc)
                *(float2*)&Cp[(long long)rA * ldc + c0] =
                    make_float2(acc[mi][ni][0], acc[mi][ni][1]);
            if (rB < Mloc)
                *(float2*)&Cp[(long long)rB * ldc + c0] =
                    make_float2(acc[mi][ni][2], acc[mi][ni][3]);
        }
    }
}

// ---------------- combine ----------------
__global__ void combine_kernel(float* __restrict__ out) {
    int t = blockIdx.x;
    __shared__ int   sslot[TOPK];
    __shared__ float sw[TOPK];
    if (threadIdx.x < TOPK) {
        sslot[threadIdx.x] = g_assign_slot[t * TOPK + threadIdx.x];
        sw[threadIdx.x]    = g_topk_w[t * TOPK + threadIdx.x];
    }
    __syncthreads();
    for (int h = threadIdx.x; h < HDIM; h += 256) {
        float acc = out[(long long)t * HDIM + h];
#pragma unroll
        for (int k = 0; k < TOPK; ++k) {
            int sl = sslot[k];
            if (sl >= 0) acc += sw[k] * g_y[(long long)sl * HDIM + h];
        }
        out[(long long)t * HDIM + h] = acc;
    }
}

// ---------------- launch ----------------
extern "C" void kernel_launch(void* const* d_in, const int* in_sizes, int n_in,
                              void* d_out, int out_size) {
    const float* x     = (const float*)d_in[0];
    const float* gw    = (const float*)d_in[2];
    const float* bias  = (const float*)d_in[3];
    const float* w13   = (const float*)d_in[4];
    const float* w2    = (const float*)d_in[5];
    const float* sgu   = (const float*)d_in[6];
    const float* sdn   = (const float*)d_in[7];
    float* out = (float*)d_out;

    cudaFuncSetAttribute(gemm_fused<true,  true,  PTR_XR, PTR_H1>,
                         cudaFuncAttributeMaxDynamicSharedMemorySize, SMEM_SZ);
    cudaFuncSetAttribute(gemm_fused<false, false, PTR_XR, PTR_HS>,
                         cudaFuncAttributeMaxDynamicSharedMemorySize, SMEM_SZ);
    cudaFuncSetAttribute(gemm_plain<true,  PTR_H1, PTR_Y>,
                         cudaFuncAttributeMaxDynamicSharedMemorySize, SMEM_SZ);
    cudaFuncSetAttribute(gemm_plain<false, PTR_HS, PTR_PARAM>,
                         cudaFuncAttributeMaxDynamicSharedMemorySize, SMEM_SZ);

    round_x_kernel<<<T * HDIM / 1024, 256>>>(x);
    routing_kernel<<<T, 256>>>(x, gw, bias);
    rank_kernel<<<1, 1024>>>();
    // routed gemm1: gathered xr @ w13 (fused silu*up, rounded) -> g_h1
    gemm_fused<true, true, PTR_XR, PTR_H1>
        <<<dim3(IDIM / 64, CAP / 128, NE), 256, SMEM_SZ>>>(
        nullptr, HDIM,
        w13, 2 * IDIM, IDIM, (long long)HDIM * 2 * IDIM,
        nullptr, IDIM, (long long)CAP * IDIM,
        CAP, HDIM);
    // routed gemm2: g_h1 @ w2 -> g_y
    gemm_plain<true, PTR_H1, PTR_Y>
        <<<dim3(HDIM / 128, CAP / 128, NE), 256, SMEM_SZ>>>(
        nullptr, IDIM, (long long)CAP * IDIM,
        w2, HDIM, (long long)IDIM * HDIM,
        nullptr, HDIM, (long long)CAP * HDIM,
        CAP, IDIM);
    // shared gemm1: xr @ shared_gate_up (fused silu*up, rounded) -> g_hs
    gemm_fused<false, false, PTR_XR, PTR_HS>
        <<<dim3(ISH / 64, T / 128, 1), 256, SMEM_SZ>>>(
        nullptr, HDIM,
        sgu, 2 * ISH, ISH, 0ll,
        nullptr, ISH, 0ll,
        T, HDIM);
    // shared gemm2: g_hs @ shared_down -> out
    gemm_plain<false, PTR_HS, PTR_PARAM>
        <<<dim3(HDIM / 128, T / 128, 1), 256, SMEM_SZ>>>(
        nullptr, ISH, 0ll,
        sdn, HDIM, 0ll,
        out, HDIM, 0ll,
        T, ISH);
    combine_kernel<<<T, 256>>>(out);
}

// round 10
// speedup vs baseline: 1.4726x; 1.3895x over previous
#include <cuda_runtime.h>
#include <cuda_fp16.h>
#include <math.h>
#include <stdint.h>

// Problem constants
#define T      512
#define HDIM   2048
#define NE     32
#define TOPK   8
#define IDIM   1408
#define NGRP   8
#define TKG    4
#define CAP    256
#define RSF    2.5f
#define ISH    2816

// SMEM geometry (fp16): A [128 rows][32k] rows 64B+16 pad; B [32k][128n] rows 256B+16 pad
#define RSA   80
#define RSB   272
#define A_STG (128 * RSA)     // 10240
#define B_STG (32 * RSB)      // 8704

// ---------------- device scratch ----------------
__device__ int    g_topk_ids[T * TOPK];
__device__ float  g_topk_w[T * TOPK];
__device__ int    g_assign_slot[T * TOPK];
__device__ int    g_slot_token[NE * CAP];
__device__ int    g_counts[NE];
__device__ __half g_xh[T * HDIM];            // fp16 x
__device__ __half g_h1[NE * CAP * IDIM];     // fp16 silu*up (routed)
__device__ __half g_hs[T * ISH];             // fp16 silu*up (shared)
__device__ float  g_y [NE * CAP * HDIM];     // fp32 routed out

#define PTR_H1 1
#define PTR_HS 3

// ---------------- helpers ----------------
__device__ __forceinline__ float silu_mul(float g, float u) {
    return (g / (1.f + expf(-g))) * u;
}
__device__ __forceinline__ void mma_f16(float* c, uint4 a, unsigned b0, unsigned b1) {
    asm("mma.sync.aligned.m16n8k16.row.col.f32.f16.f16.f32 "
        "{%0,%1,%2,%3},{%4,%5,%6,%7},{%8,%9},{%0,%1,%2,%3};"
        : "+f"(c[0]), "+f"(c[1]), "+f"(c[2]), "+f"(c[3])
        : "r"(a.x), "r"(a.y), "r"(a.z), "r"(a.w), "r"(b0), "r"(b1));
}
__device__ __forceinline__ uint4 ldsm4(unsigned addr) {
    uint4 r;
    asm volatile("ldmatrix.sync.aligned.m8n8.x4.shared.b16 {%0,%1,%2,%3}, [%4];"
                 : "=r"(r.x), "=r"(r.y), "=r"(r.z), "=r"(r.w) : "r"(addr));
    return r;
}
__device__ __forceinline__ uint4 ldsm4t(unsigned addr) {
    uint4 r;
    asm volatile("ldmatrix.sync.aligned.m8n8.x4.trans.shared.b16 {%0,%1,%2,%3}, [%4];"
                 : "=r"(r.x), "=r"(r.y), "=r"(r.z), "=r"(r.w) : "r"(addr));
    return r;
}
__device__ __forceinline__ unsigned h2u(__half2 h) {
    unsigned u; asm("mov.b32 %0, %1;" : "=r"(u) : "r"(*(unsigned*)&h)); return u;
}
__device__ __forceinline__ uint2 f4h(float4 v) {
    __half2 a = __floats2half2_rn(v.x, v.y);
    __half2 b = __floats2half2_rn(v.z, v.w);
    return make_uint2(h2u(a), h2u(b));
}
__device__ __forceinline__ void cpa16(unsigned dst, const void* src, unsigned n) {
    asm volatile("cp.async.cg.shared.global [%0], [%1], 16, %2;"
                 :: "r"(dst), "l"(src), "r"(n) : "memory");
}
#define CP_COMMIT() asm volatile("cp.async.commit_group;" ::: "memory")
#define CP_WAIT0()  asm volatile("cp.async.wait_group 0;" ::: "memory")

// ---------------- x -> fp16 ----------------
__global__ void convert_x(const float* __restrict__ x) {
    int i = (blockIdx.x * 256 + threadIdx.x) * 4;
    float4 v = *(const float4*)(x + i);
    uint2 h = f4h(v);
    *(uint2*)(g_xh + i) = h;
}

// ---------------- routing (unchanged) ----------------
__global__ void routing_kernel(const float* __restrict__ x,
                               const float* __restrict__ gw,
                               const float* __restrict__ bias) {
    int t    = blockIdx.x;
    int tid  = threadIdx.x;
    int lane = tid & 31;
    int wid  = tid >> 5;

    __shared__ float part[8][32];
    const float* xr = x + (long long)t * HDIM;
    float acc = 0.f;
    int h0 = wid * (HDIM / 8);
    for (int h = h0; h < h0 + HDIM / 8; ++h)
        acc += xr[h] * gw[h * NE + lane];
    part[wid][lane] = acc;
    __syncthreads();

    if (wid != 0) return;

    float logit = 0.f;
#pragma unroll
    for (int w = 0; w < 8; ++w) logit += part[w][lane];

    float s  = 1.f / (1.f + expf(-logit));
    float sb = s + bias[lane];

    float p   = __shfl_xor_sync(0xffffffffu, sb, 1);
    float hi  = fmaxf(sb, p), lo = fminf(sb, p);
    float hi2 = __shfl_xor_sync(0xffffffffu, hi, 2);
    float lo2 = __shfl_xor_sync(0xffffffffu, lo, 2);
    float gs  = (hi >= hi2) ? hi + fmaxf(hi2, lo) : hi2 + fmaxf(hi, lo2);

    int g = lane >> 2;
    int grank = 0;
#pragma unroll
    for (int g2 = 0; g2 < NGRP; ++g2) {
        float og = __shfl_sync(0xffffffffu, gs, g2 * 4);
        if (og > gs || (og == gs && g2 < g)) ++grank;
    }
    float cand = (grank < TKG) ? sb : -INFINITY;

    float v = cand;
    int   sel_e = 0; float sel_w = 0.f;
#pragma unroll
    for (int k = 0; k < TOPK; ++k) {
        float bv = v; int bi = lane;
#pragma unroll
        for (int off = 16; off; off >>= 1) {
            float ov = __shfl_xor_sync(0xffffffffu, bv, off);
            int   oi = __shfl_xor_sync(0xffffffffu, bi, off);
            if (ov > bv || (ov == bv && oi < bi)) { bv = ov; bi = oi; }
        }
        float ws = __shfl_sync(0xffffffffu, s, bi);
        if (lane == k)  { sel_e = bi; sel_w = ws; }
        if (lane == bi) v = -INFINITY;
    }

    float wv = (lane < TOPK) ? sel_w : 0.f;
#pragma unroll
    for (int off = 16; off; off >>= 1) wv += __shfl_xor_sync(0xffffffffu, wv, off);
    if (lane < TOPK) {
        g_topk_ids[t * TOPK + lane] = sel_e;
        g_topk_w  [t * TOPK + lane] = sel_w / wv * RSF;
    }
}

// ---------------- capacity ranking (unchanged) ----------------
__global__ void rank_kernel() {
    int w    = threadIdx.x >> 5;
    int lane = threadIdx.x & 31;
    int cnt  = 0;
    for (int i0 = 0; i0 < T * TOPK; i0 += 32) {
        int i = i0 + lane;
        int e = g_topk_ids[i];
        bool m = (e == w);
        unsigned mask = __ballot_sync(0xffffffffu, m);
        if (m) {
            int r = cnt + __popc(mask & ((1u << lane) - 1u));
            if (r < CAP) {
                g_assign_slot[i] = w * CAP + r;
                g_slot_token[w * CAP + r] = i >> 3;
            } else {
                g_assign_slot[i] = -1;
            }
        }
        cnt += __popc(mask);
    }
    if (lane == 0) g_counts[w] = min(cnt, CAP);
}

// ============================================================================
// Fused gate/up fp16 GEMM: Ch = fp16(silu(A@Bg) * (A@Bu)).
// Block M=128, N=64(gate)+64(up). 8 warps 4(m) x 2(n); warp: 2 m16 x (4g+4u) n8.
// A = g_xh/gathered rows via cp.async. B staged [k][n] fp16, ldmatrix.trans.
// ============================================================================
template <bool GATHER, bool GROUPED, int CM>
__global__ void __launch_bounds__(256, 2)
gemm_fused(int lda,
           const float* __restrict__ B, int ldb, int up_off, long long b_estride,
           int ldc, long long c_estride, int M, int Kd) {
    __shared__ __align__(16) char sm[2 * A_STG + 2 * B_STG];
    __half* Ch = (CM == PTR_H1) ? g_h1 : g_hs;

    const int e    = GROUPED ? blockIdx.z : 0;
    const int Mloc = GROUPED ? g_counts[e] : M;
    const int m0   = blockIdx.y * 128;
    if (m0 >= Mloc) return;
    const int n0   = blockIdx.x * 64;

    const float* Bp = B + (GROUPED ? (long long)e * b_estride : 0ll);
    __half*      Cp = Ch + (GROUPED ? (long long)e * c_estride : 0ll);

    const unsigned smb  = (unsigned)__cvta_generic_to_shared(sm);
    const unsigned smbB = smb + 2 * A_STG;
    const int tid  = threadIdx.x;
    const int lane = tid & 31;
    const int wid  = tid >> 5;
    const int gid  = lane >> 2;
    const int tig  = lane & 3;
    const int mt0  = (wid >> 1) * 2;       // 2 m16 tiles
    const int wn   = (wid & 1) * 4;        // gate n8 tile base (0 or 4)

    // A cp.async: row = tid>>1 (0..127), 32B half = (tid&1)
    const int arow = tid >> 1;
    const int ah   = tid & 1;
    const int gm   = m0 + arow;
    const bool avl = gm < Mloc;
    int grow;
    if (GATHER) grow = avl ? g_slot_token[e * CAP + gm] : 0;
    else        grow = avl ? gm : 0;
    const __half* asrc = g_xh + (long long)grow * lda + ah * 16;
    const unsigned adst = smb + (unsigned)arow * RSA + (unsigned)ah * 32u;
    const unsigned asz  = avl ? 16u : 0u;

    // B: kk = tid>>3 (0..31), ng = tid&7 (0-3 gate, 4-7 up), 16 f32 each
    const int kk = tid >> 3;
    const int ng = tid & 7;
    const int bcol = (ng < 4) ? (n0 + ng * 16) : (up_off + n0 + (ng - 4) * 16);
    const float* bsrc = Bp + (long long)kk * ldb + bcol;
    const unsigned bdst = smbB + (unsigned)kk * RSB + (unsigned)ng * 32u;

    float accg[2][4][4], accu[2][4][4];
#pragma unroll
    for (int mi = 0; mi < 2; ++mi)
#pragma unroll
        for (int ni = 0; ni < 4; ++ni)
#pragma unroll
            for (int r = 0; r < 4; ++r) { accg[mi][ni][r] = 0.f; accu[mi][ni][r] = 0.f; }

    // ldmatrix addresses (stage 0)
    unsigned aAddr[2], gAddr[2], uAddr[2];
#pragma unroll
    for (int mi = 0; mi < 2; ++mi)
        aAddr[mi] = smb + ((mt0 + mi) * 16 + (lane & 15)) * RSA + (lane >> 4) * 16;
#pragma unroll
    for (int j = 0; j < 2; ++j) {
        gAddr[j] = smbB + (lane & 15) * RSB + (wn + 2 * j) * 16 + (lane >> 4) * 16;
        uAddr[j] = gAddr[j] + 128;   // up tiles at +8 n8-tiles = +128B
    }

    const int S = Kd / 32;
    float4 rb[4];

    // prologue
    cpa16(adst, asrc, asz);
    cpa16(adst + 16, asrc + 8, asz);
    CP_COMMIT();
#pragma unroll
    for (int q = 0; q < 4; ++q) rb[q] = ((const float4*)bsrc)[q];
    {
        uint2 h0 = f4h(rb[0]), h1 = f4h(rb[1]), h2 = f4h(rb[2]), h3 = f4h(rb[3]);
        *(uint4*)(sm + (bdst - smb))        = make_uint4(h0.x, h0.y, h1.x, h1.y);
        *(uint4*)(sm + (bdst - smb) + 16)   = make_uint4(h2.x, h2.y, h3.x, h3.y);
    }
    CP_WAIT0();
    __syncthreads();

    for (int s = 0; s < S; ++s) {
        const unsigned buf = s & 1;
        const bool nxt = (s + 1) < S;
        if (nxt) {
            const unsigned b2 = buf ^ 1;
            const __half* src = asrc + (s + 1) * 32;
            cpa16(adst + b2 * A_STG, src, asz);
            cpa16(adst + b2 * A_STG + 16, src + 8, asz);
            CP_COMMIT();
            const float* bs = bsrc + (long long)(s + 1) * 32 * ldb;
#pragma unroll
            for (int q = 0; q < 4; ++q) rb[q] = ((const float4*)bs)[q];
        }
        const unsigned ao = buf * A_STG, bo = buf * B_STG;
#pragma unroll
        for (int kt = 0; kt < 2; ++kt) {
            const unsigned ka = kt * 32, kb = kt * 16 * RSB;
            uint4 a0 = ldsm4(aAddr[0] + ao + ka);
            uint4 a1 = ldsm4(aAddr[1] + ao + ka);
            uint4 bg0 = ldsm4t(gAddr[0] + bo + kb);
            uint4 bg1 = ldsm4t(gAddr[1] + bo + kb);
            uint4 bu0 = ldsm4t(uAddr[0] + bo + kb);
            uint4 bu1 = ldsm4t(uAddr[1] + bo + kb);
            mma_f16(accg[0][0], a0, bg0.x, bg0.y); mma_f16(accg[0][1], a0, bg0.z, bg0.w);
            mma_f16(accg[0][2], a0, bg1.x, bg1.y); mma_f16(accg[0][3], a0, bg1.z, bg1.w);
            mma_f16(accg[1][0], a1, bg0.x, bg0.y); mma_f16(accg[1][1], a1, bg0.z, bg0.w);
            mma_f16(accg[1][2], a1, bg1.x, bg1.y); mma_f16(accg[1][3], a1, bg1.z, bg1.w);
            mma_f16(accu[0][0], a0, bu0.x, bu0.y); mma_f16(accu[0][1], a0, bu0.z, bu0.w);
            mma_f16(accu[0][2], a0, bu1.x, bu1.y); mma_f16(accu[0][3], a0, bu1.z, bu1.w);
            mma_f16(accu[1][0], a1, bu0.x, bu0.y); mma_f16(accu[1][1], a1, bu0.z, bu0.w);
            mma_f16(accu[1][2], a1, bu1.x, bu1.y); mma_f16(accu[1][3], a1, bu1.z, bu1.w);
        }
        if (nxt) {
            char* bd = sm + (bdst - smb) + (buf ^ 1) * B_STG;
            uint2 h0 = f4h(rb[0]), h1 = f4h(rb[1]), h2 = f4h(rb[2]), h3 = f4h(rb[3]);
            *(uint4*)(bd)      = make_uint4(h0.x, h0.y, h1.x, h1.y);
            *(uint4*)(bd + 16) = make_uint4(h2.x, h2.y, h3.x, h3.y);
            CP_WAIT0();
        }
        __syncthreads();
    }

    // epilogue: fp16(silu(g)*u)
#pragma unroll
    for (int mi = 0; mi < 2; ++mi) {
        int rA = m0 + (mt0 + mi) * 16 + gid;
        int rB = rA + 8;
#pragma unroll
        for (int ni = 0; ni < 4; ++ni) {
            int col = n0 + (wn + ni) * 8 + 2 * tig;
            if (rA < Mloc) {
                __half2 h = __floats2half2_rn(
                    silu_mul(accg[mi][ni][0], accu[mi][ni][0]),
                    silu_mul(accg[mi][ni][1], accu[mi][ni][1]));
                *(__half2*)&Cp[(long long)rA * ldc + col] = h;
            }
            if (rB < Mloc) {
                __half2 h = __floats2half2_rn(
                    silu_mul(accg[mi][ni][2], accu[mi][ni][2]),
                    silu_mul(accg[mi][ni][3], accu[mi][ni][3]));
                *(__half2*)&Cp[(long long)rB * ldc + col] = h;
            }
        }
    }
}

// ============================================================================
// Plain fp16 GEMM: C(f32) = A(h) @ B(f32->h). Block M=128, N=128.
// 8 warps 2(m) x 4(n); warp 64x32. A cp.async, B [k][n] + ldmatrix.trans.
// ============================================================================
template <bool GROUPED, int AM, bool CY>
__global__ void __launch_bounds__(256, 2)
gemm_plain(int lda, long long a_estride,
           const float* __restrict__ B, int ldb, long long b_estride,
           float* __restrict__ Cout, int ldc, long long c_estride,
           int M, int Kd) {
    __shared__ __align__(16) char sm[2 * A_STG + 2 * B_STG];
    const __half* Ah = (AM == PTR_H1) ? g_h1 : g_hs;
    float* Cm = CY ? g_y : Cout;

    const int e    = GROUPED ? blockIdx.z : 0;
    const int Mloc = GROUPED ? g_counts[e] : M;
    const int m0   = blockIdx.y * 128;
    if (m0 >= Mloc) return;
    const int n0   = blockIdx.x * 128;

    const float*  Bp = B  + (GROUPED ? (long long)e * b_estride : 0ll);
    const __half* Ap = Ah + (GROUPED ? (long long)e * a_estride : 0ll);
    float*        Cp = Cm + (GROUPED ? (long long)e * c_estride : 0ll);

    const unsigned smb  = (unsigned)__cvta_generic_to_shared(sm);
    const unsigned smbB = smb + 2 * A_STG;
    const int tid  = threadIdx.x;
    const int lane = tid & 31;
    const int wid  = tid >> 5;
    const int gid  = lane >> 2;
    const int tig  = lane & 3;
    const int mt0  = (wid >> 2) * 4;
    const int nt0  = (wid & 3) * 4;

    const int arow = tid >> 1;
    const int ah   = tid & 1;
    const int gm   = m0 + arow;
    const bool avl = gm < Mloc;
    const __half* asrc = Ap + (long long)(avl ? gm : 0) * lda + ah * 16;
    const unsigned adst = smb + (unsigned)arow * RSA + (unsigned)ah * 32u;
    const unsigned asz  = avl ? 16u : 0u;

    const int kk = tid >> 3;
    const int ng = tid & 7;
    const float* bsrc = Bp + (long long)kk * ldb + n0 + ng * 16;
    const unsigned bdst = smbB + (unsigned)kk * RSB + (unsigned)ng * 32u;

    float acc[4][4][4];
#pragma unroll
    for (int mi = 0; mi < 4; ++mi)
#pragma unroll
        for (int ni = 0; ni < 4; ++ni)
#pragma unroll
            for (int r = 0; r < 4; ++r) acc[mi][ni][r] = 0.f;

    unsigned aAddr[4], bAddr[2];
#pragma unroll
    for (int mi = 0; mi < 4; ++mi)
        aAddr[mi] = smb + ((mt0 + mi) * 16 + (lane & 15)) * RSA + (lane >> 4) * 16;
#pragma unroll
    for (int j = 0; j < 2; ++j)
        bAddr[j] = smbB + (lane & 15) * RSB + (nt0 + 2 * j) * 16 + (lane >> 4) * 16;

    const int S = Kd / 32;
    float4 rb[4];

    cpa16(adst, asrc, asz);
    cpa16(adst + 16, asrc + 8, asz);
    CP_COMMIT();
#pragma unroll
    for (int q = 0; q < 4; ++q) rb[q] = ((const float4*)bsrc)[q];
    {
        uint2 h0 = f4h(rb[0]), h1 = f4h(rb[1]), h2 = f4h(rb[2]), h3 = f4h(rb[3]);
        *(uint4*)(sm + (bdst - smb))      = make_uint4(h0.x, h0.y, h1.x, h1.y);
        *(uint4*)(sm + (bdst - smb) + 16) = make_uint4(h2.x, h2.y, h3.x, h3.y);
    }
    CP_WAIT0();
    __syncthreads();

    for (int s = 0; s < S; ++s) {
        const unsigned buf = s & 1;
        const bool nxt = (s + 1) < S;
        if (nxt) {
            const unsigned b2 = buf ^ 1;
            const __half* src = asrc + (s + 1) * 32;
            cpa16(adst + b2 * A_STG, src, asz);
            cpa16(adst + b2 * A_STG + 16, src + 8, asz);
            CP_COMMIT();
            const float* bs = bsrc + (long long)(s + 1) * 32 * ldb;
#pragma unroll
            for (int q = 0; q < 4; ++q) rb[q] = ((const float4*)bs)[q];
        }
        const unsigned ao = buf * A_STG, bo = buf * B_STG;
#pragma unroll
        for (int kt = 0; kt < 2; ++kt) {
            const unsigned ka = kt * 32, kb = kt * 16 * RSB;
            uint4 af[4];
#pragma unroll
            for (int mi = 0; mi < 4; ++mi) af[mi] = ldsm4(aAddr[mi] + ao + ka);
            uint4 b0 = ldsm4t(bAddr[0] + bo + kb);
            uint4 b1 = ldsm4t(bAddr[1] + bo + kb);
#pragma unroll
            for (int mi = 0; mi < 4; ++mi) {
                mma_f16(acc[mi][0], af[mi], b0.x, b0.y);
                mma_f16(acc[mi][1], af[mi], b0.z, b0.w);
                mma_f16(acc[mi][2], af[mi], b1.x, b1.y);
                mma_f16(acc[mi][3], af[mi], b1.z, b1.w);
            }
        }
        if (nxt) {
            char* bd = sm + (bdst - smb) + (buf ^ 1) * B_STG;
            uint2 h0 = f4h(rb[0]), h1 = f4h(rb[1]), h2 = f4h(rb[2]), h3 = f4h(rb[3]);
            *(uint4*)(bd)      = make_uint4(h0.x, h0.y, h1.x, h1.y);
            *(uint4*)(bd + 16) = make_uint4(h2.x, h2.y, h3.x, h3.y);
            CP_WAIT0();
        }
        __syncthreads();
    }

#pragma unroll
    for (int mi = 0; mi < 4; ++mi) {
        int rA = m0 + (mt0 + mi) * 16 + gid;
        int rB = rA + 8;
#pragma unroll
        for (int ni = 0; ni < 4; ++ni) {
            int c0 = n0 + (nt0 + ni) * 8 + 2 * tig;
            if (rA < Mloc)
                *(float2*)&Cp[(long long)rA * ldc + c0] =
                    make_float2(acc[mi][ni][0], acc[mi][ni][1]);
            if (rB < Mloc)
                *(float2*)&Cp[(long long)rB * ldc + c0] =
                    make_float2(acc[mi][ni][2], acc[mi][ni][3]);
        }
    }
}

// ---------------- combine ----------------
__global__ void combine_kernel(float* __restrict__ out) {
    int t = blockIdx.x;
    __shared__ int   sslot[TOPK];
    __shared__ float sw[TOPK];
    if (threadIdx.x < TOPK) {
        sslot[threadIdx.x] = g_assign_slot[t * TOPK + threadIdx.x];
        sw[threadIdx.x]    = g_topk_w[t * TOPK + threadIdx.x];
    }
    __syncthreads();
    for (int h = threadIdx.x; h < HDIM; h += 256) {
        float acc = out[(long long)t * HDIM + h];
#pragma unroll
        for (int k = 0; k < TOPK; ++k) {
            int sl = sslot[k];
            if (sl >= 0) acc += sw[k] * g_y[(long long)sl * HDIM + h];
        }
        out[(long long)t * HDIM + h] = acc;
    }
}

// ---------------- launch ----------------
extern "C" void kernel_launch(void* const* d_in, const int* in_sizes, int n_in,
                              void* d_out, int out_size) {
    const float* x     = (const float*)d_in[0];
    const float* gw    = (const float*)d_in[2];
    const float* bias  = (const float*)d_in[3];
    const float* w13   = (const float*)d_in[4];
    const float* w2    = (const float*)d_in[5];
    const float* sgu   = (const float*)d_in[6];
    const float* sdn   = (const float*)d_in[7];
    float* out = (float*)d_out;

    convert_x<<<T * HDIM / 1024, 256>>>(x);
    routing_kernel<<<T, 256>>>(x, gw, bias);
    rank_kernel<<<1, 1024>>>();
    // routed gemm1: gathered xh @ w13 (fused silu*up) -> g_h1 (fp16)
    gemm_fused<true, true, PTR_H1><<<dim3(IDIM / 64, CAP / 128, NE), 256>>>(
        HDIM, w13, 2 * IDIM, IDIM, (long long)HDIM * 2 * IDIM,
        IDIM, (long long)CAP * IDIM, CAP, HDIM);
    // routed gemm2: g_h1 @ w2 -> g_y (fp32)
    gemm_plain<true, PTR_H1, true><<<dim3(HDIM / 128, CAP / 128, NE), 256>>>(
        IDIM, (long long)CAP * IDIM,
        w2, HDIM, (long long)IDIM * HDIM,
        nullptr, HDIM, (long long)CAP * HDIM, CAP, IDIM);
    // shared gemm1: xh @ sgu (fused silu*up) -> g_hs (fp16)
    gemm_fused<false, false, PTR_HS><<<dim3(ISH / 64, T / 128, 1), 256>>>(
        HDIM, sgu, 2 * ISH, ISH, 0ll,
        ISH, 0ll, T, HDIM);
    // shared gemm2: g_hs @ sdn -> out (fp32)
    gemm_plain<false, PTR_HS, false><<<dim3(HDIM / 128, T / 128, 1), 256>>>(
        ISH, 0ll,
        sdn, HDIM, 0ll,
        out, HDIM, 0ll, T, ISH);
    combine_kernel<<<T, 256>>>(out);
}